// round 13
// baseline (speedup 1.0000x reference)
#include <cuda_runtime.h>
#include <cstdint>
#include <math.h>

#define BATCH 4
#define SLEN  4096
#define DMODEL 512
#define SK    512          // strided keys = SLEN/8

// ---------------------------------------------------------------------------
// Scratch (__device__ globals). All hi/lo arrays use a k-permuted layout:
// within each 16-column group, value at logical k=16q+4j+i is stored at
// column 16q+4i+j (involution). This makes each mma fragment's 4 k-values
// contiguous so the GEMM loads them with a single LDS.128.
// ---------------------------------------------------------------------------
__device__ float g_qhi [(size_t)BATCH * SLEN * DMODEL];
__device__ float g_qlo [(size_t)BATCH * SLEN * DMODEL];
__device__ float g_khi [(size_t)BATCH * SK * DMODEL];
__device__ float g_klo [(size_t)BATCH * SK * DMODEL];
__device__ float g_vthi[(size_t)BATCH * DMODEL * SK];   // V^T strided: [b, d, t]
__device__ float g_vtlo[(size_t)BATCH * DMODEL * SK];
__device__ float g_scores[(size_t)BATCH * SLEN * SK];   // normal layout
__device__ float g_phi [(size_t)BATCH * SLEN * SK];     // permuted over t
__device__ float g_plo [(size_t)BATCH * SLEN * SK];

// ---------------------------------------------------------------------------
// TF32 helpers (3xTF32 split for fp32-accurate GEMM)
// ---------------------------------------------------------------------------
__device__ __forceinline__ uint32_t f2tf32(float x) {
    uint32_t r;
    asm("cvt.rna.tf32.f32 %0, %1;" : "=r"(r) : "f"(x));
    return r;
}
__device__ __forceinline__ void split_tf32(float x, uint32_t& hi, uint32_t& lo) {
    hi = f2tf32(x);
    lo = f2tf32(x - __uint_as_float(hi));
}

__device__ __forceinline__ void mma_tf32(float* c, const uint32_t* a, const uint32_t* b) {
    asm volatile(
        "mma.sync.aligned.m16n8k8.row.col.f32.tf32.tf32.f32 "
        "{%0,%1,%2,%3}, {%4,%5,%6,%7}, {%8,%9}, {%0,%1,%2,%3};\n"
        : "+f"(c[0]), "+f"(c[1]), "+f"(c[2]), "+f"(c[3])
        : "r"(a[0]), "r"(a[1]), "r"(a[2]), "r"(a[3]), "r"(b[0]), "r"(b[1]));
}

__device__ __forceinline__ uint32_t smem_u32(const void* p) {
    uint32_t a;
    asm("{ .reg .u64 t; cvta.to.shared.u64 t, %1; cvt.u32.u64 %0, t; }" : "=r"(a) : "l"(p));
    return a;
}
__device__ __forceinline__ void cp16(uint32_t dst, const void* src) {
    asm volatile("cp.async.cg.shared.global [%0], [%1], 16;" :: "r"(dst), "l"(src));
}

// ---------------------------------------------------------------------------
// Split kernels: write k-permuted hi/lo arrays. One thread = one 16-col group.
// ---------------------------------------------------------------------------
__device__ __forceinline__ void split_permute_store(const float v[16],
                                                    float* __restrict__ dhi,
                                                    float* __restrict__ dlo) {
    float oh[16], ol[16];
    #pragma unroll
    for (int i = 0; i < 4; ++i)
        #pragma unroll
        for (int j = 0; j < 4; ++j) {
            uint32_t h, l;
            split_tf32(v[4 * j + i], h, l);
            oh[4 * i + j] = __uint_as_float(h);
            ol[4 * i + j] = __uint_as_float(l);
        }
    #pragma unroll
    for (int i = 0; i < 4; ++i) {
        *(float4*)(dhi + 4 * i) = make_float4(oh[4*i], oh[4*i+1], oh[4*i+2], oh[4*i+3]);
        *(float4*)(dlo + 4 * i) = make_float4(ol[4*i], ol[4*i+1], ol[4*i+2], ol[4*i+3]);
    }
}

__global__ __launch_bounds__(128) void split_q(const float* __restrict__ q) {
    const float scale = 0.0441941738241592f;  // 1/sqrt(512)
    int row = blockIdx.x * 4 + (threadIdx.x >> 5);
    int grp = threadIdx.x & 31;
    size_t base = (size_t)row * DMODEL + grp * 16;
    float v[16];
    #pragma unroll
    for (int j = 0; j < 4; ++j) {
        float4 x = *(const float4*)(q + base + 4 * j);
        v[4*j+0] = x.x * scale; v[4*j+1] = x.y * scale;
        v[4*j+2] = x.z * scale; v[4*j+3] = x.w * scale;
    }
    split_permute_store(v, g_qhi + base, g_qlo + base);
}

__global__ __launch_bounds__(128) void split_k(const float* __restrict__ kin) {
    int r = blockIdx.x * 4 + (threadIdx.x >> 5);   // 0..2047 (= b*512 + t)
    int grp = threadIdx.x & 31;
    int b = r >> 9, t = r & 511;
    size_t sbase = ((size_t)(b * SLEN + 8 * t)) * DMODEL + grp * 16;
    size_t dbase = (size_t)r * DMODEL + grp * 16;
    float v[16];
    #pragma unroll
    for (int j = 0; j < 4; ++j) {
        float4 x = *(const float4*)(kin + sbase + 4 * j);
        v[4*j+0] = x.x; v[4*j+1] = x.y; v[4*j+2] = x.z; v[4*j+3] = x.w;
    }
    split_permute_store(v, g_khi + dbase, g_klo + dbase);
}

// V^T strided + split + t-permutation: vt[b, d, perm(t)] = V[b, 8t, d]
__global__ __launch_bounds__(256) void split_vt(const float* __restrict__ v) {
    __shared__ float tile[32][33];
    int b  = blockIdx.z;
    int t0 = blockIdx.x * 32;
    int d0 = blockIdx.y * 32;
    int tx = threadIdx.x & 31, ty = threadIdx.x >> 5;
    #pragma unroll
    for (int q8 = 0; q8 < 4; ++q8) {
        int tt = ty + q8 * 8;
        tile[tt][tx] = v[((size_t)b * SLEN + 8 * (t0 + tt)) * DMODEL + d0 + tx];
    }
    __syncthreads();
    int txp = (tx & 16) | ((tx & 3) << 2) | ((tx >> 2) & 3);   // permute within 16-group
    #pragma unroll
    for (int q8 = 0; q8 < 4; ++q8) {
        int dd = ty + q8 * 8;
        uint32_t hi, lo;
        split_tf32(tile[tx][dd], hi, lo);
        size_t o = ((size_t)b * DMODEL + d0 + dd) * SK + t0 + txp;
        g_vthi[o] = __uint_as_float(hi);
        g_vtlo[o] = __uint_as_float(lo);
    }
}

// ---------------------------------------------------------------------------
// Mask kernel: mask[i][j] = (j%8==0 && j<=i) ? 1 : 0
// ---------------------------------------------------------------------------
__global__ __launch_bounds__(256) void mask_kernel(float* __restrict__ mout) {
    int i = blockIdx.x;
    float4* m4 = (float4*)(mout + (size_t)i * SLEN);
    #pragma unroll
    for (int kk = 0; kk < 4; ++kk) {
        int g = threadIdx.x + kk * 256;
        float x = (((g & 1) == 0) && (4 * g <= i)) ? 1.0f : 0.0f;
        m4[g] = make_float4(x, 0.0f, 0.0f, 0.0f);
    }
}

// ---------------------------------------------------------------------------
// 3xTF32 mma.sync GEMM, 128x128 tile, K-chunk 16, cp.async double-buffered.
// Operands pre-split + k-permuted so fragments load with single LDS.128.
// All of ahi/alo/bhi/blo/outp have inner row stride 512 floats.
// ---------------------------------------------------------------------------
#define CHUNK_FLOATS 2048                      // one 128x16 tile
#define STAGE_FLOATS (4 * CHUNK_FLOATS)        // Ahi, Alo, Bhi, Blo
#define SMEM_DYN     (2 * STAGE_FLOATS * 4)    // 64 KB

__device__ __forceinline__ void issue_chunk_load(float* st, int c, int tid,
                                                 const float* const bases[4]) {
    #pragma unroll
    for (int i = 0; i < 8; ++i) {
        int slot = tid + i * 256;              // 0..2047
        int tile = slot >> 9;                  // constant per unrolled i
        int w    = slot & 511;
        int r    = w >> 2;                     // row 0..127
        int qd   = w & 3;                      // float4 within 16-col row
        cp16(smem_u32(st + tile * CHUNK_FLOATS + r * 16 + qd * 4),
             bases[tile] + (size_t)r * 512 + c * 16 + qd * 4);
    }
    asm volatile("cp.async.commit_group;" ::: "memory");
}

__device__ __forceinline__ void gemm128_body(const float* __restrict__ ahi,
                                             const float* __restrict__ alo,
                                             const float* __restrict__ bhi,
                                             const float* __restrict__ blo,
                                             float* __restrict__ outp,
                                             int nch) {
    extern __shared__ __align__(16) float smem[];
    const int tid  = threadIdx.x;
    const int warp = tid >> 5, lane = tid & 31;
    const int wm = warp >> 1, wn = warp & 1;   // 4x2 warp grid, warp tile 32(m) x 64(n)
    const int g  = lane >> 2, t4 = lane & 3;
    const float* bases[4] = {ahi, alo, bhi, blo};

    float acc[2][8][4] = {};

    issue_chunk_load(smem, 0, tid, bases);

    for (int c = 0; c < nch; ++c) {
        asm volatile("cp.async.wait_group 0;" ::: "memory");
        __syncthreads();   // all warps done with prior compute + chunk c landed
        if (c + 1 < nch)
            issue_chunk_load(smem + ((c + 1) & 1) * STAGE_FLOATS, c + 1, tid, bases);

        const float* sA_hi = smem + (c & 1) * STAGE_FLOATS;
        const float* sA_lo = sA_hi + CHUNK_FLOATS;
        const float* sB_hi = sA_hi + 2 * CHUNK_FLOATS;
        const float* sB_lo = sA_hi + 3 * CHUNK_FLOATS;

        // A fragments for the full 16-k chunk: one LDS.128 per row per hi/lo
        float4 fah[2][2], fal[2][2];
        #pragma unroll
        for (int m2 = 0; m2 < 2; ++m2) {
            int r0 = wm * 32 + m2 * 16 + g;
            fah[m2][0] = *(const float4*)(sA_hi + r0 * 16 + t4 * 4);
            fah[m2][1] = *(const float4*)(sA_hi + (r0 + 8) * 16 + t4 * 4);
            fal[m2][0] = *(const float4*)(sA_lo + r0 * 16 + t4 * 4);
            fal[m2][1] = *(const float4*)(sA_lo + (r0 + 8) * 16 + t4 * 4);
        }
        #pragma unroll
        for (int n2 = 0; n2 < 8; ++n2) {
            int n = wn * 64 + n2 * 8 + g;
            float4 fbh = *(const float4*)(sB_hi + n * 16 + t4 * 4);
            float4 fbl = *(const float4*)(sB_lo + n * 16 + t4 * 4);
            // phase 0 (k = 0..7 of chunk): components .x (k=t4), .y (k=t4+4)
            {
                uint32_t bh[2] = {__float_as_uint(fbh.x), __float_as_uint(fbh.y)};
                uint32_t bl[2] = {__float_as_uint(fbl.x), __float_as_uint(fbl.y)};
                #pragma unroll
                for (int m2 = 0; m2 < 2; ++m2) {
                    uint32_t ah[4] = {__float_as_uint(fah[m2][0].x), __float_as_uint(fah[m2][1].x),
                                      __float_as_uint(fah[m2][0].y), __float_as_uint(fah[m2][1].y)};
                    uint32_t al[4] = {__float_as_uint(fal[m2][0].x), __float_as_uint(fal[m2][1].x),
                                      __float_as_uint(fal[m2][0].y), __float_as_uint(fal[m2][1].y)};
                    mma_tf32(acc[m2][n2], ah, bh);
                    mma_tf32(acc[m2][n2], ah, bl);
                    mma_tf32(acc[m2][n2], al, bh);
                }
            }
            // phase 1 (k = 8..15): components .z (k=t4+8), .w (k=t4+12)
            {
                uint32_t bh[2] = {__float_as_uint(fbh.z), __float_as_uint(fbh.w)};
                uint32_t bl[2] = {__float_as_uint(fbl.z), __float_as_uint(fbl.w)};
                #pragma unroll
                for (int m2 = 0; m2 < 2; ++m2) {
                    uint32_t ah[4] = {__float_as_uint(fah[m2][0].z), __float_as_uint(fah[m2][1].z),
                                      __float_as_uint(fah[m2][0].w), __float_as_uint(fah[m2][1].w)};
                    uint32_t al[4] = {__float_as_uint(fal[m2][0].z), __float_as_uint(fal[m2][1].z),
                                      __float_as_uint(fal[m2][0].w), __float_as_uint(fal[m2][1].w)};
                    mma_tf32(acc[m2][n2], ah, bh);
                    mma_tf32(acc[m2][n2], ah, bl);
                    mma_tf32(acc[m2][n2], al, bh);
                }
            }
        }
    }

    // epilogue (identical mapping to the R1 pass)
    #pragma unroll
    for (int m2 = 0; m2 < 2; ++m2) {
        int r0 = wm * 32 + m2 * 16 + g;
        #pragma unroll
        for (int n2 = 0; n2 < 8; ++n2) {
            int c0 = wn * 64 + n2 * 8 + 2 * t4;
            *(float2*)(outp + (size_t)r0 * 512 + c0) =
                make_float2(acc[m2][n2][0], acc[m2][n2][1]);
            *(float2*)(outp + (size_t)(r0 + 8) * 512 + c0) =
                make_float2(acc[m2][n2][2], acc[m2][n2][3]);
        }
    }
}

// ---------------------------------------------------------------------------
// GEMM wrappers.  NOTE: no min-blocks clause — R12's __launch_bounds__(256,2)
// capped regs at 128 and (theory) spilled the 32 fragment registers into
// local memory inside the hot loop.  Let ptxas take ~150-170 regs, occ 1.
// ---------------------------------------------------------------------------
__global__ __launch_bounds__(256) void gemm_qk_tc() {
    const int nj = blockIdx.x, mi = blockIdx.y, b = blockIdx.z;
    if (128 * nj > 16 * mi + 15) return;   // fully-masked tile
    const float* ah = g_qhi + ((size_t)b * SLEN + mi * 128) * DMODEL;
    const float* al = g_qlo + ((size_t)b * SLEN + mi * 128) * DMODEL;
    const float* bh = g_khi + ((size_t)b * SK + nj * 128) * DMODEL;
    const float* bl = g_klo + ((size_t)b * SK + nj * 128) * DMODEL;
    float* op = g_scores + ((size_t)b * SLEN + mi * 128) * SK + nj * 128;
    gemm128_body(ah, al, bh, bl, op, DMODEL / 16);
}

__global__ __launch_bounds__(256) void gemm_pv_tc(float* __restrict__ outO) {
    const int dj = blockIdx.x, mi = blockIdx.y, b = blockIdx.z;
    const float* ah = g_phi + ((size_t)b * SLEN + mi * 128) * SK;
    const float* al = g_plo + ((size_t)b * SLEN + mi * 128) * SK;
    const float* bh = g_vthi + ((size_t)b * DMODEL + dj * 128) * SK;
    const float* bl = g_vtlo + ((size_t)b * DMODEL + dj * 128) * SK;
    float* op = outO + ((size_t)b * SLEN + mi * 128) * DMODEL + dj * 128;
    gemm128_body(ah, al, bh, bl, op, mi + 1);   // causal: t <= 16*mi+15
}

// ---------------------------------------------------------------------------
// Softmax: per-row masked softmax over 512 strided scores.
// Writes pre-split+permuted P (hi/lo) + the dense 4096-wide weights row.
// ---------------------------------------------------------------------------
__global__ __launch_bounds__(128) void softmax_kernel(float* __restrict__ wout) {
    const int row = blockIdx.x;
    const int i   = row & (SLEN - 1);
    const int tid = threadIdx.x;
    const int tmax = i >> 3;
    const int t0 = tid * 4;

    const float4 s4 = *((const float4*)(g_scores + (size_t)row * SK) + tid);
    float s[4] = {s4.x, s4.y, s4.z, s4.w};

    float m = -INFINITY;
    #pragma unroll
    for (int j = 0; j < 4; ++j)
        if (t0 + j <= tmax) m = fmaxf(m, s[j]);

    __shared__ float redm[4];
    #pragma unroll
    for (int off = 16; off; off >>= 1) m = fmaxf(m, __shfl_xor_sync(0xffffffffu, m, off));
    if ((tid & 31) == 0) redm[tid >> 5] = m;
    __syncthreads();
    m = fmaxf(fmaxf(redm[0], redm[1]), fmaxf(redm[2], redm[3]));

    float e[4];
    float sum = 0.0f;
    #pragma unroll
    for (int j = 0; j < 4; ++j) {
        e[j] = (t0 + j <= tmax) ? expf(s[j] - m) : 0.0f;
        sum += e[j];
    }
    __shared__ float reds[4];
    #pragma unroll
    for (int off = 16; off; off >>= 1) sum += __shfl_xor_sync(0xffffffffu, sum, off);
    if ((tid & 31) == 0) reds[tid >> 5] = sum;
    __syncthreads();
    sum = reds[0] + reds[1] + reds[2] + reds[3];

    const float inv = 1.0f / sum;
    float p[4];
    #pragma unroll
    for (int j = 0; j < 4; ++j) {
        p[j] = e[j] * inv;
        uint32_t hi, lo;
        split_tf32(p[j], hi, lo);
        // permuted column: t = 4*tid + j -> (t & ~15) | ((t&3)<<2) | ((t>>2)&3)
        int t = t0 + j;
        int col = (t & ~15) | ((t & 3) << 2) | ((t >> 2) & 3);
        g_phi[(size_t)row * SK + col] = __uint_as_float(hi);
        g_plo[(size_t)row * SK + col] = __uint_as_float(lo);
    }

    // dense attn_weights row: j = 8t carries p[t], everything else 0
    float4* w4 = (float4*)(wout + (size_t)row * SLEN) + tid * 8;
    #pragma unroll
    for (int gg = 0; gg < 8; ++gg) {
        float x = (gg & 1) ? 0.0f : p[gg >> 1];
        w4[gg] = make_float4(x, 0.0f, 0.0f, 0.0f);
    }
}

// ---------------------------------------------------------------------------
// Launch: out layout = [output (B*S*D)] [attn_weights (B*S*S)] [mask (S*S)]
// ---------------------------------------------------------------------------
extern "C" void kernel_launch(void* const* d_in, const int* in_sizes, int n_in,
                              void* d_out, int out_size) {
    const float* q = (const float*)d_in[0];
    const float* k = (const float*)d_in[1];
    const float* v = (const float*)d_in[2];

    float* o_out = (float*)d_out;
    float* w_out = o_out + (size_t)BATCH * SLEN * DMODEL;
    float* m_out = w_out + (size_t)BATCH * SLEN * SLEN;

    cudaFuncSetAttribute(gemm_qk_tc, cudaFuncAttributeMaxDynamicSharedMemorySize, SMEM_DYN);
    cudaFuncSetAttribute(gemm_pv_tc, cudaFuncAttributeMaxDynamicSharedMemorySize, SMEM_DYN);

    mask_kernel   <<<SLEN, 256>>>(m_out);
    split_q       <<<BATCH * SLEN / 4, 128>>>(q);
    split_k       <<<BATCH * SK / 4, 128>>>(k);
    split_vt      <<<dim3(SK / 32, DMODEL / 32, BATCH), 256>>>(v);
    gemm_qk_tc    <<<dim3(4, 32, BATCH), 256, SMEM_DYN>>>();
    softmax_kernel<<<BATCH * SLEN, 128>>>(w_out);
    gemm_pv_tc    <<<dim3(4, 32, BATCH), 256, SMEM_DYN>>>(o_out);
}

// round 15
// speedup vs baseline: 1.2211x; 1.2211x over previous
#include <cuda_runtime.h>
#include <cuda_bf16.h>
#include <cstdint>
#include <math.h>

// Problem constants
#define BATCH 4
#define SLEN  4096
#define DMODEL 512
#define SK    512          // number of strided keys (SLEN / 8)

// Scratch (allocation-free rule: __device__ globals)
__device__ float g_scores[(size_t)BATCH * SLEN * SK];  // 33.5 MB
__device__ float g_probs [(size_t)BATCH * SLEN * SK];  // 33.5 MB

// ---------------------------------------------------------------------------
// TF32 helpers (3xTF32 split for fp32-accurate tensor-core GEMM)
// ---------------------------------------------------------------------------
__device__ __forceinline__ uint32_t f2tf32(float x) {
    uint32_t r;
    asm("cvt.rna.tf32.f32 %0, %1;" : "=r"(r) : "f"(x));
    return r;
}

__device__ __forceinline__ void split_tf32(float x, uint32_t& hi, uint32_t& lo) {
    hi = f2tf32(x);
    lo = f2tf32(x - __uint_as_float(hi));
}

__device__ __forceinline__ void mma_tf32(float* c, const uint32_t* a, const uint32_t* b) {
    asm volatile(
        "mma.sync.aligned.m16n8k8.row.col.f32.tf32.tf32.f32 "
        "{%0,%1,%2,%3}, {%4,%5,%6,%7}, {%8,%9}, {%0,%1,%2,%3};\n"
        : "+f"(c[0]), "+f"(c[1]), "+f"(c[2]), "+f"(c[3])
        : "r"(a[0]), "r"(a[1]), "r"(a[2]), "r"(a[3]), "r"(b[0]), "r"(b[1]));
}

__device__ __forceinline__ uint32_t smem_u32(const void* p) {
    uint32_t a;
    asm("{ .reg .u64 t; cvta.to.shared.u64 t, %1; cvt.u32.u64 %0, t; }" : "=r"(a) : "l"(p));
    return a;
}
__device__ __forceinline__ void cp16(uint32_t dst, const void* src) {
    asm volatile("cp.async.cg.shared.global [%0], [%1], 16;" :: "r"(dst), "l"(src));
}

// ---------------------------------------------------------------------------
// Kernel 1: mask region.  mask[i][j] = (j % 8 == 0) && (j <= i), as 1.0/0.0
// ---------------------------------------------------------------------------
__global__ __launch_bounds__(256) void mask_kernel(float* __restrict__ mout) {
    int i = blockIdx.x;
    float4* m4 = (float4*)(mout + (size_t)i * SLEN);
    #pragma unroll
    for (int kk = 0; kk < 4; ++kk) {
        int g = threadIdx.x + kk * 256;           // float4 index 0..1023, j0 = 4g
        float x = (((g & 1) == 0) && (4 * g <= i)) ? 1.0f : 0.0f;
        m4[g] = make_float4(x, 0.0f, 0.0f, 0.0f);
    }
}

// ---------------------------------------------------------------------------
// GEMM tiling constants (identical to the 354us R1 kernel)
// ---------------------------------------------------------------------------
#define BM 128
#define BN 128
#define BK 16
#define APAD 20      // smem row stride (floats) for [128 x 16] tiles
#define VPAD 136     // smem row stride (floats) for [16 x 128] V tile

// ---------------------------------------------------------------------------
// Kernel 2: scores = (scale*Q) @ K_strided^T   (3xTF32)
// R1 structure + cp.async double-buffering (the ONE change this round).
// ---------------------------------------------------------------------------
__global__ __launch_bounds__(256) void gemm_qk(const float* __restrict__ q,
                                               const float* __restrict__ kmat) {
    const int nj = blockIdx.x, mi = blockIdx.y, b = blockIdx.z;
    if (128 * nj > 16 * mi + 15) return;   // no query in this m-tile can see these keys

    __shared__ float As[2][BM * APAD];
    __shared__ float Bs[2][BN * APAD];

    const int tid  = threadIdx.x;
    const int warp = tid >> 5, lane = tid & 31;
    const int wm = warp >> 1, wn = warp & 1;       // 4x2 warp grid -> warp tile 32(m) x 64(n)
    const int g  = lane >> 2, t4 = lane & 3;

    const float scale = 0.0441941738241592f;       // 1/sqrt(512)

    float acc[2][8][4] = {};

    // async tile fill for chunk kc into stage st
    auto issue_load = [&](int st, int kc) {
        #pragma unroll
        for (int s = 0; s < 2; ++s) {
            int slot = tid + s * 256;              // 0..511 float4 slots
            int r = slot >> 2, c4 = slot & 3;
            cp16(smem_u32(&As[st][r * APAD + c4 * 4]),
                 q + ((size_t)(b * SLEN + mi * BM + r)) * DMODEL + kc * BK + c4 * 4);
            cp16(smem_u32(&Bs[st][r * APAD + c4 * 4]),
                 kmat + ((size_t)(b * SLEN + 8 * (nj * BN + r))) * DMODEL + kc * BK + c4 * 4);
        }
        asm volatile("cp.async.commit_group;" ::: "memory");
    };

    issue_load(0, 0);

    for (int kc = 0; kc < DMODEL / BK; ++kc) {
        asm volatile("cp.async.wait_group 0;" ::: "memory");
        __syncthreads();                            // chunk kc landed; prior compute done
        if (kc + 1 < DMODEL / BK) issue_load((kc + 1) & 1, kc + 1);
        const float* sA = As[kc & 1];
        const float* sB = Bs[kc & 1];

        #pragma unroll
        for (int kkk = 0; kkk < BK; kkk += 8) {
            uint32_t ah[2][4], al[2][4];
            #pragma unroll
            for (int m2 = 0; m2 < 2; ++m2) {
                int r0 = wm * 32 + m2 * 16 + g;
                split_tf32(scale * sA[r0 * APAD + kkk + t4],          ah[m2][0], al[m2][0]);
                split_tf32(scale * sA[(r0 + 8) * APAD + kkk + t4],    ah[m2][1], al[m2][1]);
                split_tf32(scale * sA[r0 * APAD + kkk + t4 + 4],      ah[m2][2], al[m2][2]);
                split_tf32(scale * sA[(r0 + 8) * APAD + kkk + t4 + 4],ah[m2][3], al[m2][3]);
            }
            #pragma unroll
            for (int n2 = 0; n2 < 8; ++n2) {
                int n = wn * 64 + n2 * 8 + g;
                uint32_t bh[2], bl[2];
                split_tf32(sB[n * APAD + kkk + t4],     bh[0], bl[0]);
                split_tf32(sB[n * APAD + kkk + t4 + 4], bh[1], bl[1]);
                #pragma unroll
                for (int m2 = 0; m2 < 2; ++m2) {
                    mma_tf32(acc[m2][n2], ah[m2], bh);
                    mma_tf32(acc[m2][n2], ah[m2], bl);
                    mma_tf32(acc[m2][n2], al[m2], bh);
                }
            }
        }
    }

    float* outb = g_scores + (size_t)b * SLEN * SK;
    #pragma unroll
    for (int m2 = 0; m2 < 2; ++m2) {
        int r0 = mi * BM + wm * 32 + m2 * 16 + g;
        #pragma unroll
        for (int n2 = 0; n2 < 8; ++n2) {
            int c0 = nj * BN + wn * 64 + n2 * 8 + 2 * t4;
            *(float2*)(outb + (size_t)r0 * SK + c0)       = make_float2(acc[m2][n2][0], acc[m2][n2][1]);
            *(float2*)(outb + (size_t)(r0 + 8) * SK + c0) = make_float2(acc[m2][n2][2], acc[m2][n2][3]);
        }
    }
}

// ---------------------------------------------------------------------------
// Kernel 3: per-row masked softmax over 512 strided scores (identical to R1).
// ---------------------------------------------------------------------------
__global__ __launch_bounds__(128) void softmax_kernel(float* __restrict__ wout) {
    const int row = blockIdx.x;                     // 0..16383 (= b*4096 + i)
    const int i   = row & (SLEN - 1);
    const int tid = threadIdx.x;
    const int tmax = i >> 3;                        // largest valid t
    const int t0 = tid * 4;

    const float4 s4 = *((const float4*)(g_scores + (size_t)row * SK) + tid);
    float s[4] = {s4.x, s4.y, s4.z, s4.w};

    float m = -INFINITY;
    #pragma unroll
    for (int j = 0; j < 4; ++j)
        if (t0 + j <= tmax) m = fmaxf(m, s[j]);

    __shared__ float redm[4];
    #pragma unroll
    for (int off = 16; off; off >>= 1) m = fmaxf(m, __shfl_xor_sync(0xffffffffu, m, off));
    if ((tid & 31) == 0) redm[tid >> 5] = m;
    __syncthreads();
    m = fmaxf(fmaxf(redm[0], redm[1]), fmaxf(redm[2], redm[3]));

    float e[4];
    float sum = 0.0f;
    #pragma unroll
    for (int j = 0; j < 4; ++j) {
        e[j] = (t0 + j <= tmax) ? expf(s[j] - m) : 0.0f;
        sum += e[j];
    }
    __shared__ float reds[4];
    #pragma unroll
    for (int off = 16; off; off >>= 1) sum += __shfl_xor_sync(0xffffffffu, sum, off);
    if ((tid & 31) == 0) reds[tid >> 5] = sum;
    __syncthreads();
    sum = reds[0] + reds[1] + reds[2] + reds[3];

    const float inv = 1.0f / sum;
    float p[4];
    #pragma unroll
    for (int j = 0; j < 4; ++j) p[j] = e[j] * inv;

    // compact probs for the PV GEMM
    *((float4*)(g_probs + (size_t)row * SK) + tid) = make_float4(p[0], p[1], p[2], p[3]);

    // dense attn_weights row
    float4* w4 = (float4*)(wout + (size_t)row * SLEN) + tid * 8;
    #pragma unroll
    for (int gg = 0; gg < 8; ++gg) {
        float x = (gg & 1) ? 0.0f : p[gg >> 1];
        w4[gg] = make_float4(x, 0.0f, 0.0f, 0.0f);
    }
}

// ---------------------------------------------------------------------------
// Kernel 4: output = P @ V_strided   (3xTF32), R1 structure + double-buffer.
// ---------------------------------------------------------------------------
__global__ __launch_bounds__(256) void gemm_pv(const float* __restrict__ v,
                                               float* __restrict__ outO) {
    const int dj = blockIdx.x, mi = blockIdx.y, b = blockIdx.z;

    __shared__ float As[2][BM * APAD];
    __shared__ float Vs[2][16 * VPAD];

    const int tid  = threadIdx.x;
    const int warp = tid >> 5, lane = tid & 31;
    const int wm = warp >> 1, wn = warp & 1;
    const int g  = lane >> 2, t4 = lane & 3;

    float acc[2][8][4] = {};

    const int nchunks = mi + 1;   // t only goes up to 16*mi+15 for this query tile

    auto issue_load = [&](int st, int kc) {
        #pragma unroll
        for (int s = 0; s < 2; ++s) {
            int slot = tid + s * 256;
            {   // A tile [128 x 16] of P
                int r = slot >> 2, c4 = slot & 3;
                cp16(smem_u32(&As[st][r * APAD + c4 * 4]),
                     g_probs + ((size_t)(b * SLEN + mi * BM + r)) * SK + kc * BK + c4 * 4);
            }
            {   // V tile [16 t x 128 d]
                int tr = slot >> 5, c4 = slot & 31;
                cp16(smem_u32(&Vs[st][tr * VPAD + c4 * 4]),
                     v + ((size_t)(b * SLEN + 8 * (kc * 16 + tr))) * DMODEL + dj * 128 + c4 * 4);
            }
        }
        asm volatile("cp.async.commit_group;" ::: "memory");
    };

    issue_load(0, 0);

    for (int kc = 0; kc < nchunks; ++kc) {
        asm volatile("cp.async.wait_group 0;" ::: "memory");
        __syncthreads();
        if (kc + 1 < nchunks) issue_load((kc + 1) & 1, kc + 1);
        const float* sA = As[kc & 1];
        const float* sV = Vs[kc & 1];

        #pragma unroll
        for (int kkk = 0; kkk < BK; kkk += 8) {
            uint32_t ah[2][4], al[2][4];
            #pragma unroll
            for (int m2 = 0; m2 < 2; ++m2) {
                int r0 = wm * 32 + m2 * 16 + g;
                split_tf32(sA[r0 * APAD + kkk + t4],           ah[m2][0], al[m2][0]);
                split_tf32(sA[(r0 + 8) * APAD + kkk + t4],     ah[m2][1], al[m2][1]);
                split_tf32(sA[r0 * APAD + kkk + t4 + 4],       ah[m2][2], al[m2][2]);
                split_tf32(sA[(r0 + 8) * APAD + kkk + t4 + 4], ah[m2][3], al[m2][3]);
            }
            #pragma unroll
            for (int n2 = 0; n2 < 8; ++n2) {
                int n = wn * 64 + n2 * 8 + g;              // d index within the 128 tile
                uint32_t bh[2], bl[2];
                split_tf32(sV[(kkk + t4) * VPAD + n],     bh[0], bl[0]);
                split_tf32(sV[(kkk + t4 + 4) * VPAD + n], bh[1], bl[1]);
                #pragma unroll
                for (int m2 = 0; m2 < 2; ++m2) {
                    mma_tf32(acc[m2][n2], ah[m2], bh);
                    mma_tf32(acc[m2][n2], ah[m2], bl);
                    mma_tf32(acc[m2][n2], al[m2], bh);
                }
            }
        }
    }

    #pragma unroll
    for (int m2 = 0; m2 < 2; ++m2) {
        int r0 = mi * BM + wm * 32 + m2 * 16 + g;
        #pragma unroll
        for (int n2 = 0; n2 < 8; ++n2) {
            int c0 = dj * 128 + wn * 64 + n2 * 8 + 2 * t4;
            *(float2*)(outO + ((size_t)(b * SLEN + r0)) * DMODEL + c0) =
                make_float2(acc[m2][n2][0], acc[m2][n2][1]);
            *(float2*)(outO + ((size_t)(b * SLEN + r0 + 8)) * DMODEL + c0) =
                make_float2(acc[m2][n2][2], acc[m2][n2][3]);
        }
    }
}

// ---------------------------------------------------------------------------
// Launch: out layout = [output (B*S*D)] [attn_weights (B*S*S)] [mask (S*S)]
// ---------------------------------------------------------------------------
extern "C" void kernel_launch(void* const* d_in, const int* in_sizes, int n_in,
                              void* d_out, int out_size) {
    const float* q = (const float*)d_in[0];
    const float* k = (const float*)d_in[1];
    const float* v = (const float*)d_in[2];

    float* o_out = (float*)d_out;
    float* w_out = o_out + (size_t)BATCH * SLEN * DMODEL;
    float* m_out = w_out + (size_t)BATCH * SLEN * SLEN;

    mask_kernel   <<<SLEN, 256>>>(m_out);
    gemm_qk       <<<dim3(4, 32, BATCH), 256>>>(q, k);
    softmax_kernel<<<BATCH * SLEN, 128>>>(w_out);
    gemm_pv       <<<dim3(4, 32, BATCH), 256>>>(v, o_out);
}

// round 16
// speedup vs baseline: 1.3811x; 1.1310x over previous
#include <cuda_runtime.h>
#include <cuda_bf16.h>
#include <cstdint>
#include <math.h>

// Problem constants
#define BATCH 4
#define SLEN  4096
#define DMODEL 512
#define SK    512          // number of strided keys (SLEN / 8)

// Scratch (allocation-free rule: __device__ globals)
__device__ float g_scores[(size_t)BATCH * SLEN * SK];  // 33.5 MB
__device__ float g_probs [(size_t)BATCH * SLEN * SK];  // 33.5 MB

// ---------------------------------------------------------------------------
// TF32 helpers (3xTF32 split for fp32-accurate tensor-core GEMM)
// ---------------------------------------------------------------------------
__device__ __forceinline__ uint32_t f2tf32(float x) {
    uint32_t r;
    asm("cvt.rna.tf32.f32 %0, %1;" : "=r"(r) : "f"(x));
    return r;
}

__device__ __forceinline__ void split_tf32(float x, uint32_t& hi, uint32_t& lo) {
    hi = f2tf32(x);
    lo = f2tf32(x - __uint_as_float(hi));
}

__device__ __forceinline__ void mma_tf32(float* c, const uint32_t* a, const uint32_t* b) {
    asm volatile(
        "mma.sync.aligned.m16n8k8.row.col.f32.tf32.tf32.f32 "
        "{%0,%1,%2,%3}, {%4,%5,%6,%7}, {%8,%9}, {%0,%1,%2,%3};\n"
        : "+f"(c[0]), "+f"(c[1]), "+f"(c[2]), "+f"(c[3])
        : "r"(a[0]), "r"(a[1]), "r"(a[2]), "r"(a[3]), "r"(b[0]), "r"(b[1]));
}

__device__ __forceinline__ uint32_t smem_u32(const void* p) {
    uint32_t a;
    asm("{ .reg .u64 t; cvta.to.shared.u64 t, %1; cvt.u32.u64 %0, t; }" : "=r"(a) : "l"(p));
    return a;
}
__device__ __forceinline__ void cp16(uint32_t dst, const void* src) {
    asm volatile("cp.async.cg.shared.global [%0], [%1], 16;" :: "r"(dst), "l"(src));
}

// ---------------------------------------------------------------------------
// Kernel 1: mask region.  mask[i][j] = (j % 8 == 0) && (j <= i), as 1.0/0.0
// ---------------------------------------------------------------------------
__global__ __launch_bounds__(256) void mask_kernel(float* __restrict__ mout) {
    int i = blockIdx.x;
    float4* m4 = (float4*)(mout + (size_t)i * SLEN);
    #pragma unroll
    for (int kk = 0; kk < 4; ++kk) {
        int g = threadIdx.x + kk * 256;           // float4 index 0..1023, j0 = 4g
        float x = (((g & 1) == 0) && (4 * g <= i)) ? 1.0f : 0.0f;
        m4[g] = make_float4(x, 0.0f, 0.0f, 0.0f);
    }
}

// ---------------------------------------------------------------------------
// GEMM tiling: BM=128, BN=64, BK=16.  8 warps as 4(wm) x 2(wn); warp tile
// 32(m) x 32(n) -> acc = 32 regs/thread.  __launch_bounds__(256,3) -> 84-reg
// cap -> 3 CTAs/SM (24 warps) instead of 2 CTAs at the old 127-reg footprint.
// ---------------------------------------------------------------------------
#define BM 128
#define BN 64
#define BK 16
#define APAD 20      // smem row stride (floats) for [rows x 16] tiles
#define VPAD 72      // smem row stride (floats) for [16 x 64] V tile

// ---------------------------------------------------------------------------
// Kernel 2: scores = (scale*Q) @ K_strided^T   (3xTF32)
// ---------------------------------------------------------------------------
__global__ __launch_bounds__(256, 3) void gemm_qk(const float* __restrict__ q,
                                                  const float* __restrict__ kmat) {
    const int nj = blockIdx.x, mi = blockIdx.y, b = blockIdx.z;
    if (64 * nj > 16 * mi + 15) return;   // no query in this m-tile can see these keys

    __shared__ float As[2][BM * APAD];
    __shared__ float Bs[2][BN * APAD];

    const int tid  = threadIdx.x;
    const int warp = tid >> 5, lane = tid & 31;
    const int wm = warp >> 1, wn = warp & 1;       // 4x2 warp grid -> warp tile 32(m) x 32(n)
    const int g  = lane >> 2, t4 = lane & 3;

    const float scale = 0.0441941738241592f;       // 1/sqrt(512)

    float acc[2][4][4] = {};

    auto issue_load = [&](int st, int kc) {
        #pragma unroll
        for (int s = 0; s < 2; ++s) {              // A: 512 float4 slots
            int slot = tid + s * 256;
            int r = slot >> 2, c4 = slot & 3;
            cp16(smem_u32(&As[st][r * APAD + c4 * 4]),
                 q + ((size_t)(b * SLEN + mi * BM + r)) * DMODEL + kc * BK + c4 * 4);
        }
        {                                          // B: 256 float4 slots
            int r = tid >> 2, c4 = tid & 3;
            cp16(smem_u32(&Bs[st][r * APAD + c4 * 4]),
                 kmat + ((size_t)(b * SLEN + 8 * (nj * BN + r))) * DMODEL + kc * BK + c4 * 4);
        }
        asm volatile("cp.async.commit_group;" ::: "memory");
    };

    issue_load(0, 0);

    for (int kc = 0; kc < DMODEL / BK; ++kc) {
        asm volatile("cp.async.wait_group 0;" ::: "memory");
        __syncthreads();
        if (kc + 1 < DMODEL / BK) issue_load((kc + 1) & 1, kc + 1);
        const float* sA = As[kc & 1];
        const float* sB = Bs[kc & 1];

        #pragma unroll
        for (int kkk = 0; kkk < BK; kkk += 8) {
            uint32_t ah[2][4], al[2][4];
            #pragma unroll
            for (int m2 = 0; m2 < 2; ++m2) {
                int r0 = wm * 32 + m2 * 16 + g;
                split_tf32(scale * sA[r0 * APAD + kkk + t4],          ah[m2][0], al[m2][0]);
                split_tf32(scale * sA[(r0 + 8) * APAD + kkk + t4],    ah[m2][1], al[m2][1]);
                split_tf32(scale * sA[r0 * APAD + kkk + t4 + 4],      ah[m2][2], al[m2][2]);
                split_tf32(scale * sA[(r0 + 8) * APAD + kkk + t4 + 4],ah[m2][3], al[m2][3]);
            }
            #pragma unroll
            for (int n2 = 0; n2 < 4; ++n2) {
                int n = wn * 32 + n2 * 8 + g;
                uint32_t bh[2], bl[2];
                split_tf32(sB[n * APAD + kkk + t4],     bh[0], bl[0]);
                split_tf32(sB[n * APAD + kkk + t4 + 4], bh[1], bl[1]);
                #pragma unroll
                for (int m2 = 0; m2 < 2; ++m2) {
                    mma_tf32(acc[m2][n2], ah[m2], bh);
                    mma_tf32(acc[m2][n2], ah[m2], bl);
                    mma_tf32(acc[m2][n2], al[m2], bh);
                }
            }
        }
    }

    float* outb = g_scores + (size_t)b * SLEN * SK;
    #pragma unroll
    for (int m2 = 0; m2 < 2; ++m2) {
        int r0 = mi * BM + wm * 32 + m2 * 16 + g;
        #pragma unroll
        for (int n2 = 0; n2 < 4; ++n2) {
            int c0 = nj * BN + wn * 32 + n2 * 8 + 2 * t4;
            *(float2*)(outb + (size_t)r0 * SK + c0)       = make_float2(acc[m2][n2][0], acc[m2][n2][1]);
            *(float2*)(outb + (size_t)(r0 + 8) * SK + c0) = make_float2(acc[m2][n2][2], acc[m2][n2][3]);
        }
    }
}

// ---------------------------------------------------------------------------
// Kernel 3: per-row masked softmax over 512 strided scores (unchanged).
// ---------------------------------------------------------------------------
__global__ __launch_bounds__(128) void softmax_kernel(float* __restrict__ wout) {
    const int row = blockIdx.x;                     // 0..16383 (= b*4096 + i)
    const int i   = row & (SLEN - 1);
    const int tid = threadIdx.x;
    const int tmax = i >> 3;
    const int t0 = tid * 4;

    const float4 s4 = *((const float4*)(g_scores + (size_t)row * SK) + tid);
    float s[4] = {s4.x, s4.y, s4.z, s4.w};

    float m = -INFINITY;
    #pragma unroll
    for (int j = 0; j < 4; ++j)
        if (t0 + j <= tmax) m = fmaxf(m, s[j]);

    __shared__ float redm[4];
    #pragma unroll
    for (int off = 16; off; off >>= 1) m = fmaxf(m, __shfl_xor_sync(0xffffffffu, m, off));
    if ((tid & 31) == 0) redm[tid >> 5] = m;
    __syncthreads();
    m = fmaxf(fmaxf(redm[0], redm[1]), fmaxf(redm[2], redm[3]));

    float e[4];
    float sum = 0.0f;
    #pragma unroll
    for (int j = 0; j < 4; ++j) {
        e[j] = (t0 + j <= tmax) ? expf(s[j] - m) : 0.0f;
        sum += e[j];
    }
    __shared__ float reds[4];
    #pragma unroll
    for (int off = 16; off; off >>= 1) sum += __shfl_xor_sync(0xffffffffu, sum, off);
    if ((tid & 31) == 0) reds[tid >> 5] = sum;
    __syncthreads();
    sum = reds[0] + reds[1] + reds[2] + reds[3];

    const float inv = 1.0f / sum;
    float p[4];
    #pragma unroll
    for (int j = 0; j < 4; ++j) p[j] = e[j] * inv;

    *((float4*)(g_probs + (size_t)row * SK) + tid) = make_float4(p[0], p[1], p[2], p[3]);

    float4* w4 = (float4*)(wout + (size_t)row * SLEN) + tid * 8;
    #pragma unroll
    for (int gg = 0; gg < 8; ++gg) {
        float x = (gg & 1) ? 0.0f : p[gg >> 1];
        w4[gg] = make_float4(x, 0.0f, 0.0f, 0.0f);
    }
}

// ---------------------------------------------------------------------------
// Kernel 4: output = P @ V_strided   (3xTF32)
// ---------------------------------------------------------------------------
__global__ __launch_bounds__(256, 3) void gemm_pv(const float* __restrict__ v,
                                                  float* __restrict__ outO) {
    const int dj = blockIdx.x, mi = blockIdx.y, b = blockIdx.z;

    __shared__ float As[2][BM * APAD];
    __shared__ float Vs[2][16 * VPAD];

    const int tid  = threadIdx.x;
    const int warp = tid >> 5, lane = tid & 31;
    const int wm = warp >> 1, wn = warp & 1;
    const int g  = lane >> 2, t4 = lane & 3;

    float acc[2][4][4] = {};

    const int nchunks = mi + 1;   // t only goes up to 16*mi+15 for this query tile

    auto issue_load = [&](int st, int kc) {
        #pragma unroll
        for (int s = 0; s < 2; ++s) {              // A (P) tile [128 x 16]
            int slot = tid + s * 256;
            int r = slot >> 2, c4 = slot & 3;
            cp16(smem_u32(&As[st][r * APAD + c4 * 4]),
                 g_probs + ((size_t)(b * SLEN + mi * BM + r)) * SK + kc * BK + c4 * 4);
        }
        {                                          // V tile [16 t x 64 d]
            int tr = tid >> 4, c4 = tid & 15;
            cp16(smem_u32(&Vs[st][tr * VPAD + c4 * 4]),
                 v + ((size_t)(b * SLEN + 8 * (kc * 16 + tr))) * DMODEL + dj * BN + c4 * 4);
        }
        asm volatile("cp.async.commit_group;" ::: "memory");
    };

    issue_load(0, 0);

    for (int kc = 0; kc < nchunks; ++kc) {
        asm volatile("cp.async.wait_group 0;" ::: "memory");
        __syncthreads();
        if (kc + 1 < nchunks) issue_load((kc + 1) & 1, kc + 1);
        const float* sA = As[kc & 1];
        const float* sV = Vs[kc & 1];

        #pragma unroll
        for (int kkk = 0; kkk < BK; kkk += 8) {
            uint32_t ah[2][4], al[2][4];
            #pragma unroll
            for (int m2 = 0; m2 < 2; ++m2) {
                int r0 = wm * 32 + m2 * 16 + g;
                split_tf32(sA[r0 * APAD + kkk + t4],           ah[m2][0], al[m2][0]);
                split_tf32(sA[(r0 + 8) * APAD + kkk + t4],     ah[m2][1], al[m2][1]);
                split_tf32(sA[r0 * APAD + kkk + t4 + 4],       ah[m2][2], al[m2][2]);
                split_tf32(sA[(r0 + 8) * APAD + kkk + t4 + 4], ah[m2][3], al[m2][3]);
            }
            #pragma unroll
            for (int n2 = 0; n2 < 4; ++n2) {
                int n = wn * 32 + n2 * 8 + g;              // d index within the 64 tile
                uint32_t bh[2], bl[2];
                split_tf32(sV[(kkk + t4) * VPAD + n],     bh[0], bl[0]);
                split_tf32(sV[(kkk + t4 + 4) * VPAD + n], bh[1], bl[1]);
                #pragma unroll
                for (int m2 = 0; m2 < 2; ++m2) {
                    mma_tf32(acc[m2][n2], ah[m2], bh);
                    mma_tf32(acc[m2][n2], ah[m2], bl);
                    mma_tf32(acc[m2][n2], al[m2], bh);
                }
            }
        }
    }

    #pragma unroll
    for (int m2 = 0; m2 < 2; ++m2) {
        int r0 = mi * BM + wm * 32 + m2 * 16 + g;
        #pragma unroll
        for (int n2 = 0; n2 < 4; ++n2) {
            int c0 = dj * BN + wn * 32 + n2 * 8 + 2 * t4;
            *(float2*)(outO + ((size_t)(b * SLEN + r0)) * DMODEL + c0) =
                make_float2(acc[m2][n2][0], acc[m2][n2][1]);
            *(float2*)(outO + ((size_t)(b * SLEN + r0 + 8)) * DMODEL + c0) =
                make_float2(acc[m2][n2][2], acc[m2][n2][3]);
        }
    }
}

// ---------------------------------------------------------------------------
// Launch: out layout = [output (B*S*D)] [attn_weights (B*S*S)] [mask (S*S)]
// ---------------------------------------------------------------------------
extern "C" void kernel_launch(void* const* d_in, const int* in_sizes, int n_in,
                              void* d_out, int out_size) {
    const float* q = (const float*)d_in[0];
    const float* k = (const float*)d_in[1];
    const float* v = (const float*)d_in[2];

    float* o_out = (float*)d_out;
    float* w_out = o_out + (size_t)BATCH * SLEN * DMODEL;
    float* m_out = w_out + (size_t)BATCH * SLEN * SLEN;

    mask_kernel   <<<SLEN, 256>>>(m_out);
    gemm_qk       <<<dim3(8, 32, BATCH), 256>>>(q, k);
    softmax_kernel<<<BATCH * SLEN, 128>>>(w_out);
    gemm_pv       <<<dim3(8, 32, BATCH), 256>>>(v, o_out);
}